// round 1
// baseline (speedup 1.0000x reference)
#include <cuda_runtime.h>

#define BDIM   256
#define TQ     900
#define TK     200
#define BATCH  128
#define NEG    (-1e30f)
#define LOG2E  1.4426950408889634f
#define LN2    0.6931471805599453f
#define CHUNK  8

// Per-batch losses; scratch via __device__ global (no allocation allowed).
__device__ float g_losses[BATCH];

__device__ __forceinline__ float ex2f(float x) {
    float y; asm("ex2.approx.ftz.f32 %0, %1;" : "=f"(y) : "f"(x)); return y;
}
__device__ __forceinline__ float lg2f(float x) {
    float y; asm("lg2.approx.ftz.f32 %0, %1;" : "=f"(y) : "f"(x)); return y;
}
__device__ __forceinline__ void cp16(void* s, const void* g) {
    unsigned sa = (unsigned)__cvta_generic_to_shared(s);
    asm volatile("cp.async.cg.shared.global [%0], [%1], 16;" :: "r"(sa), "l"(g));
}

// One CTA per batch element. 256 threads (8 warps).
// Thread j (j<=200) owns states s=2j (even, blank) and s=2j+1 (odd, label j+1).
// Only odd states are communicated through shared memory (double-buffered).
// attn rows are staged through smem in 8-row chunks via cp.async (double-buffered);
// per-chunk, warp w computes the log-softmax denominator of row w from the SAME
// smem chunk, so global memory is read exactly once.
__global__ __launch_bounds__(BDIM, 1)
void ctc_kernel(const float* __restrict__ attn,
                const int*   __restrict__ in_lens,
                const int*   __restrict__ out_lens)
{
    __shared__ __align__(16) float s_chunk[2][CHUNK][TK];
    __shared__ float s_dn[2][CHUNK];
    __shared__ float s_odd[2][208];
    __shared__ float s_hi;

    const int b    = blockIdx.x;
    const int tid  = threadIdx.x;
    const int lane = tid & 31;
    const int wid  = tid >> 5;
    const int L       = in_lens[b];    // 100..200
    const int out_len = out_lens[b];   // 700..900
    const float* attn_b = attn + (size_t)b * TQ * TK;

    // Prologue: stage chunk 0 (rows t=0..7)
    for (int i = tid; i < 50 * CHUNK; i += BDIM) {
        int r = i / 50, seg = i % 50;
        if (r < out_len) cp16(&s_chunk[0][r][seg * 4], attn_b + (size_t)r * TK + seg * 4);
    }
    asm volatile("cp.async.commit_group;");

    float a_e = NEG, a_o = NEG;   // log2-domain alphas for states 2j, 2j+1
    int pb = 0;
    const int nchunks = (out_len + CHUNK - 1) / CHUNK;

    for (int c = 0; c < nchunks; ++c) {
        const int buf = c & 1;
        const int t0  = c * CHUNK;

        // Prefetch next chunk, then wait for current.
        if (c + 1 < nchunks) {
            const int t0n = t0 + CHUNK;
            for (int i = tid; i < 50 * CHUNK; i += BDIM) {
                int r = i / 50, seg = i % 50;
                int t = t0n + r;
                if (t < out_len) cp16(&s_chunk[buf ^ 1][r][seg * 4],
                                      attn_b + (size_t)t * TK + seg * 4);
            }
            asm volatile("cp.async.commit_group;");
            asm volatile("cp.async.wait_group 1;");
        } else {
            asm volatile("cp.async.wait_group 0;");
        }
        __syncthreads();

        // Log-softmax denominator (log2 domain) for this chunk's rows:
        // denom2 = log2( sum_k e^{x_k} ) over 200 logits + blank logit (-1.0).
        {
            int t = t0 + wid;
            if (t < out_len) {
                float v[7];
                float m = -1.0f;   // include blank logit in the max
                #pragma unroll
                for (int i2 = 0; i2 < 7; ++i2) {
                    int k = lane + 32 * i2;
                    v[i2] = (k < TK) ? s_chunk[buf][wid][k] : NEG;
                    m = fmaxf(m, v[i2]);
                }
                #pragma unroll
                for (int off = 16; off; off >>= 1)
                    m = fmaxf(m, __shfl_xor_sync(0xffffffffu, m, off));
                float s = 0.f;
                #pragma unroll
                for (int i2 = 0; i2 < 7; ++i2) s += ex2f((v[i2] - m) * LOG2E);
                #pragma unroll
                for (int off = 16; off; off >>= 1)
                    s += __shfl_xor_sync(0xffffffffu, s, off);
                s += ex2f((-1.0f - m) * LOG2E);   // blank term
                if (lane == 0) s_dn[buf][wid] = m * LOG2E + lg2f(s);
            }
        }
        __syncthreads();

        const int nr = min(CHUNK, out_len - t0);
        for (int r = 0; r < nr; ++r) {
            const int   t  = t0 + r;
            const float dn = s_dn[buf][r];

            if (t == 0) {
                // alpha0: state0 = blank emit, state1 = label-1 emit, rest NEG.
                float x00 = s_chunk[buf][0][0];
                a_e = (tid == 0) ? (-LOG2E - dn)        : NEG;
                a_o = (tid == 0) ? (x00 * LOG2E - dn)   : NEG;
                if (tid < 200) s_odd[0][tid] = a_o;
                __syncthreads();
                pb = 0;
                continue;
            }

            // neighbor odd state alpha[2j-1]
            float a1 = (tid >= 1 && tid <= 200) ? s_odd[pb][tid - 1] : NEG;

            // even state 2j:  LSE2(a_e, a1) + blank emit  (softplus form: 2 MUFU)
            float ne;
            {
                float M = fmaxf(a_e, a1);
                float d = -fabsf(a_e - a1);
                ne = M + lg2f(1.0f + ex2f(d)) + (-LOG2E - dn);
            }
            // odd state 2j+1: LSE3(a_o, a_e_old, a1) + label emit (mask: emit=0 if j>=L)
            float no;
            {
                float xv   = (tid < 200) ? s_chunk[buf][r][tid] : 0.0f;
                float emit = (tid < L) ? (xv * LOG2E - dn) : 0.0f;
                float M    = fmaxf(a_o, fmaxf(a_e, a1));
                float ssum = ex2f(a_o - M) + ex2f(a_e - M) + ex2f(a1 - M);
                no = M + lg2f(ssum) + emit;
            }

            if (tid < 200) s_odd[pb ^ 1][tid] = no;
            __syncthreads();
            pb ^= 1;
            if (tid <= 200) { a_e = ne; a_o = no; }
        }
    }

    // fin = alpha at t = out_len-1.  hi = fin[2L] (even, thread L),
    // lo = fin[2L-1] (odd, thread L-1, sits in s_odd[pb]).
    if (tid == L) s_hi = a_e;
    __syncthreads();
    if (tid == 0) {
        float hi = s_hi;
        float lo = s_odd[pb][L - 1];
        float M  = fmaxf(hi, lo);
        float l2 = M + lg2f(ex2f(hi - M) + ex2f(lo - M));
        float loss = -l2 * LN2;
        if (loss > 1e20f) loss = 0.0f;
        g_losses[b] = loss / (float)L;
    }
}

// Deterministic mean over the 128 per-batch losses.
__global__ void reduce_kernel(float* __restrict__ out)
{
    __shared__ float sb[BATCH];
    sb[threadIdx.x] = g_losses[threadIdx.x];
    __syncthreads();
    if (threadIdx.x == 0) {
        float s = 0.f;
        for (int i = 0; i < BATCH; ++i) s += sb[i];
        out[0] = s * (1.0f / BATCH);
    }
}

extern "C" void kernel_launch(void* const* d_in, const int* in_sizes, int n_in,
                              void* d_out, int out_size)
{
    const float* attn     = (const float*)d_in[0];
    const int*   in_lens  = (const int*)d_in[1];
    const int*   out_lens = (const int*)d_in[2];
    (void)in_sizes; (void)n_in; (void)out_size;

    ctc_kernel<<<BATCH, BDIM>>>(attn, in_lens, out_lens);
    reduce_kernel<<<1, BATCH>>>((float*)d_out);
}